// round 10
// baseline (speedup 1.0000x reference)
#include <cuda_runtime.h>

// DDA_PU_loss: loss = sum_pos (recon-dv)^2 * (1-alpha)/2 + sum_neg (recon-dv)^2 * alpha/2
// Inputs (metadata order):
//  0: drug_virus_reconstruct f32 [8192,16384]
//  1: drug_virus             f32 [8192,16384]
//  2: drug_virus_mask        f32 (unused by reference math)
//  3: pos_x_index  [524288]   int32 OR int64 (detected at runtime)
//  4: pos_y_index  [524288]
//  5: neg_x_index  [2097152]
//  6: neg_y_index  [2097152]
//  7: alpha        f32 scalar
// Output: f32 scalar.

#define N_VIRUS_LOG2 14  // row width 16384, fixed shape

__device__ double g_acc[2];  // [0]=pos_se, [1]=neg_se
__device__ int    g_is64;    // 1 if index arrays are int64, 0 if int32

// Detect index dtype: for int64 little-endian nonnegative values < 2^13,
// every odd 32-bit word (high half) is zero. For int32 uniform in [0,8192),
// the chance all 128 sampled odd words are zero is (1/8192)^128 ~ 0.
__global__ void setup_kernel(const unsigned* __restrict__ px_words) {
    if (threadIdx.x == 0) {
        int all_zero = 1;
        #pragma unroll 1
        for (int i = 1; i < 256; i += 2) all_zero &= (px_words[i] == 0u);
        g_is64  = all_zero;
        g_acc[0] = 0.0;
        g_acc[1] = 0.0;
    }
}

__global__ __launch_bounds__(256) void gather_se_kernel(
    const float* __restrict__ recon,
    const float* __restrict__ dv,
    const void*  __restrict__ px_raw,
    const void*  __restrict__ py_raw,
    int n_pos,
    const void*  __restrict__ nx_raw,
    const void*  __restrict__ ny_raw,
    int n_neg)
{
    const int tid    = blockIdx.x * blockDim.x + threadIdx.x;
    const int stride = gridDim.x * blockDim.x;
    const int is64   = g_is64;  // uniform across grid

    double pos_acc = 0.0;
    double neg_acc = 0.0;

    if (!is64) {
        const int* __restrict__ px = (const int*)px_raw;
        const int* __restrict__ py = (const int*)py_raw;
        const int* __restrict__ nx = (const int*)nx_raw;
        const int* __restrict__ ny = (const int*)ny_raw;

        for (int i = tid; i < n_pos; i += stride) {
            unsigned idx = ((unsigned)__ldg(&px[i]) << N_VIRUS_LOG2) + (unsigned)__ldg(&py[i]);
            float d = __ldg(&recon[idx]) - __ldg(&dv[idx]);
            pos_acc += (double)d * (double)d;
        }
        for (int i = tid; i < n_neg; i += stride) {
            unsigned idx = ((unsigned)__ldg(&nx[i]) << N_VIRUS_LOG2) + (unsigned)__ldg(&ny[i]);
            float d = __ldg(&recon[idx]) - __ldg(&dv[idx]);
            neg_acc += (double)d * (double)d;
        }
    } else {
        const long long* __restrict__ px = (const long long*)px_raw;
        const long long* __restrict__ py = (const long long*)py_raw;
        const long long* __restrict__ nx = (const long long*)nx_raw;
        const long long* __restrict__ ny = (const long long*)ny_raw;

        for (int i = tid; i < n_pos; i += stride) {
            long long idx = (__ldg(&px[i]) << N_VIRUS_LOG2) + __ldg(&py[i]);
            float d = __ldg(&recon[idx]) - __ldg(&dv[idx]);
            pos_acc += (double)d * (double)d;
        }
        for (int i = tid; i < n_neg; i += stride) {
            long long idx = (__ldg(&nx[i]) << N_VIRUS_LOG2) + __ldg(&ny[i]);
            float d = __ldg(&recon[idx]) - __ldg(&dv[idx]);
            neg_acc += (double)d * (double)d;
        }
    }

    // warp reduction
    #pragma unroll
    for (int off = 16; off > 0; off >>= 1) {
        pos_acc += __shfl_down_sync(0xFFFFFFFFu, pos_acc, off);
        neg_acc += __shfl_down_sync(0xFFFFFFFFu, neg_acc, off);
    }
    if ((threadIdx.x & 31) == 0) {
        atomicAdd(&g_acc[0], pos_acc);
        atomicAdd(&g_acc[1], neg_acc);
    }
}

__global__ void finalize_kernel(const float* __restrict__ alpha, float* __restrict__ out) {
    double a = (double)alpha[0];
    out[0] = (float)(g_acc[0] * ((1.0 - a) * 0.5) + g_acc[1] * (a * 0.5));
}

extern "C" void kernel_launch(void* const* d_in, const int* in_sizes, int n_in,
                              void* d_out, int out_size)
{
    const float* recon = (const float*)d_in[0];
    const float* dv    = (const float*)d_in[1];
    const void*  px    = d_in[3];
    const void*  py    = d_in[4];
    const void*  nx    = d_in[5];
    const void*  ny    = d_in[6];
    const float* alpha = (const float*)d_in[7];
    float*       out   = (float*)d_out;

    int n_pos = in_sizes[3];
    int n_neg = in_sizes[5];

    setup_kernel<<<1, 32>>>((const unsigned*)px);

    const int threads = 256;
    const int blocks  = 148 * 16;  // ~606K threads
    gather_se_kernel<<<blocks, threads>>>(recon, dv, px, py, n_pos, nx, ny, n_neg);

    finalize_kernel<<<1, 1>>>(alpha, out);
}

// round 11
// speedup vs baseline: 1.1985x; 1.1985x over previous
#include <cuda_runtime.h>

// DDA_PU_loss: loss = sum_pos (recon-dv)^2 * (1-alpha)/2 + sum_neg (recon-dv)^2 * alpha/2
// Inputs (metadata order):
//  0: drug_virus_reconstruct f32 [8192,16384]
//  1: drug_virus             f32 [8192,16384]
//  2: drug_virus_mask        f32 (unused by reference math)
//  3: pos_x_index  [524288]   int32 OR int64 (detected at runtime)
//  4: pos_y_index  [524288]
//  5: neg_x_index  [2097152]
//  6: neg_y_index  [2097152]
//  7: alpha        f32 scalar
// Output: f32 scalar.

#define N_VIRUS_LOG2 14  // row width 16384, fixed shape

__device__ double g_acc[2];  // [0]=pos_se, [1]=neg_se
__device__ int    g_is64;    // 1 if index arrays are int64, 0 if int32

// Detect index dtype: for int64 little-endian nonnegative values < 2^13,
// every odd 32-bit word (high half) is zero. For int32 uniform in [0,8192),
// the chance all 128 sampled odd words are zero is (1/8192)^128 ~ 0.
__global__ void setup_kernel(const unsigned* __restrict__ px_words) {
    if (threadIdx.x == 0) {
        int all_zero = 1;
        #pragma unroll 1
        for (int i = 1; i < 256; i += 2) all_zero &= (px_words[i] == 0u);
        g_is64  = all_zero;
        g_acc[0] = 0.0;
        g_acc[1] = 0.0;
    }
}

__global__ __launch_bounds__(256) void gather_se_kernel(
    const float* __restrict__ recon,
    const float* __restrict__ dv,
    const void*  __restrict__ px_raw,
    const void*  __restrict__ py_raw,
    int n_pos,
    const void*  __restrict__ nx_raw,
    const void*  __restrict__ ny_raw,
    int n_neg)
{
    const int tid    = blockIdx.x * blockDim.x + threadIdx.x;
    const int stride = gridDim.x * blockDim.x;
    const int is64   = g_is64;  // uniform across grid

    double pos_acc = 0.0;
    double neg_acc = 0.0;

    if (!is64) {
        const int* __restrict__ px = (const int*)px_raw;
        const int* __restrict__ py = (const int*)py_raw;
        const int* __restrict__ nx = (const int*)nx_raw;
        const int* __restrict__ ny = (const int*)ny_raw;

        for (int i = tid; i < n_pos; i += stride) {
            unsigned idx = ((unsigned)__ldg(&px[i]) << N_VIRUS_LOG2) + (unsigned)__ldg(&py[i]);
            float d = __ldg(&recon[idx]) - __ldg(&dv[idx]);
            pos_acc += (double)d * (double)d;
        }
        for (int i = tid; i < n_neg; i += stride) {
            unsigned idx = ((unsigned)__ldg(&nx[i]) << N_VIRUS_LOG2) + (unsigned)__ldg(&ny[i]);
            float d = __ldg(&recon[idx]) - __ldg(&dv[idx]);
            neg_acc += (double)d * (double)d;
        }
    } else {
        const long long* __restrict__ px = (const long long*)px_raw;
        const long long* __restrict__ py = (const long long*)py_raw;
        const long long* __restrict__ nx = (const long long*)nx_raw;
        const long long* __restrict__ ny = (const long long*)ny_raw;

        for (int i = tid; i < n_pos; i += stride) {
            long long idx = (__ldg(&px[i]) << N_VIRUS_LOG2) + __ldg(&py[i]);
            float d = __ldg(&recon[idx]) - __ldg(&dv[idx]);
            pos_acc += (double)d * (double)d;
        }
        for (int i = tid; i < n_neg; i += stride) {
            long long idx = (__ldg(&nx[i]) << N_VIRUS_LOG2) + __ldg(&ny[i]);
            float d = __ldg(&recon[idx]) - __ldg(&dv[idx]);
            neg_acc += (double)d * (double)d;
        }
    }

    // warp reduction
    #pragma unroll
    for (int off = 16; off > 0; off >>= 1) {
        pos_acc += __shfl_down_sync(0xFFFFFFFFu, pos_acc, off);
        neg_acc += __shfl_down_sync(0xFFFFFFFFu, neg_acc, off);
    }
    if ((threadIdx.x & 31) == 0) {
        atomicAdd(&g_acc[0], pos_acc);
        atomicAdd(&g_acc[1], neg_acc);
    }
}

__global__ void finalize_kernel(const float* __restrict__ alpha, float* __restrict__ out) {
    double a = (double)alpha[0];
    out[0] = (float)(g_acc[0] * ((1.0 - a) * 0.5) + g_acc[1] * (a * 0.5));
}

extern "C" void kernel_launch(void* const* d_in, const int* in_sizes, int n_in,
                              void* d_out, int out_size)
{
    const float* recon = (const float*)d_in[0];
    const float* dv    = (const float*)d_in[1];
    const void*  px    = d_in[3];
    const void*  py    = d_in[4];
    const void*  nx    = d_in[5];
    const void*  ny    = d_in[6];
    const float* alpha = (const float*)d_in[7];
    float*       out   = (float*)d_out;

    int n_pos = in_sizes[3];
    int n_neg = in_sizes[5];

    setup_kernel<<<1, 32>>>((const unsigned*)px);

    const int threads = 256;
    const int blocks  = 148 * 16;  // ~606K threads
    gather_se_kernel<<<blocks, threads>>>(recon, dv, px, py, n_pos, nx, ny, n_neg);

    finalize_kernel<<<1, 1>>>(alpha, out);
}

// round 13
// speedup vs baseline: 1.5414x; 1.2862x over previous
#include <cuda_runtime.h>

// DDA_PU_loss: loss = sum_pos (recon-dv)^2 * (1-alpha)/2 + sum_neg (recon-dv)^2 * alpha/2
// Inputs (metadata order):
//  0: drug_virus_reconstruct f32 [8192,16384]
//  1: drug_virus             f32 [8192,16384]
//  2: drug_virus_mask        f32 (unused by reference math)
//  3: pos_x_index  [524288]   int32 OR int64 (detected at runtime)
//  4: pos_y_index  [524288]
//  5: neg_x_index  [2097152]
//  6: neg_y_index  [2097152]
//  7: alpha        f32 scalar
// Output: f32 scalar.

#define N_VIRUS_LOG2 14  // row width 16384, fixed shape

__device__ double g_acc[2];  // [0]=pos_se, [1]=neg_se
__device__ int    g_is64;    // 1 if index arrays are int64, 0 if int32

// Detect index dtype in parallel (1 warp): for little-endian int64 values in
// [0, 8192), every odd 32-bit word (high half) is zero. For int32 uniform in
// [0,8192), P(128 random words all zero) = (1/8192)^128 ~ 0.
__global__ void setup_kernel(const unsigned* __restrict__ px_words) {
    int t = threadIdx.x;  // 0..31
    bool zero = true;
    #pragma unroll
    for (int j = 0; j < 4; j++)
        zero &= (px_words[8 * t + 2 * j + 1] == 0u);
    int all = __all_sync(0xFFFFFFFFu, zero);
    if (t == 0) {
        g_is64  = all ? 1 : 0;
        g_acc[0] = 0.0;
        g_acc[1] = 0.0;
    }
}

// ---- int32 fast path: vec4 index loads, 8 independent gathers per iter ----
__device__ __forceinline__ double gather4_i32(
    const float* __restrict__ recon, const float* __restrict__ dv,
    const int4* __restrict__ x4, const int4* __restrict__ y4,
    int n4, int tid, int stride, double acc)
{
    for (int i = tid; i < n4; i += stride) {
        int4 xv = __ldg(&x4[i]);
        int4 yv = __ldg(&y4[i]);
        unsigned i0 = ((unsigned)xv.x << N_VIRUS_LOG2) + (unsigned)yv.x;
        unsigned i1 = ((unsigned)xv.y << N_VIRUS_LOG2) + (unsigned)yv.y;
        unsigned i2 = ((unsigned)xv.z << N_VIRUS_LOG2) + (unsigned)yv.z;
        unsigned i3 = ((unsigned)xv.w << N_VIRUS_LOG2) + (unsigned)yv.w;
        float r0 = __ldg(recon + i0), r1 = __ldg(recon + i1);
        float r2 = __ldg(recon + i2), r3 = __ldg(recon + i3);
        float v0 = __ldg(dv + i0),    v1 = __ldg(dv + i1);
        float v2 = __ldg(dv + i2),    v3 = __ldg(dv + i3);
        float d0 = r0 - v0, d1 = r1 - v1, d2 = r2 - v2, d3 = r3 - v3;
        float s = fmaf(d0, d0, fmaf(d1, d1, fmaf(d2, d2, d3 * d3)));
        acc += (double)s;
    }
    return acc;
}

// ---- int64 path: vec2 index loads, 4 independent gathers per iter ----
__device__ __forceinline__ double gather2_i64(
    const float* __restrict__ recon, const float* __restrict__ dv,
    const longlong2* __restrict__ x2, const longlong2* __restrict__ y2,
    int n2, int tid, int stride, double acc)
{
    for (int i = tid; i < n2; i += stride) {
        longlong2 xv = __ldg(&x2[i]);
        longlong2 yv = __ldg(&y2[i]);
        long long i0 = (xv.x << N_VIRUS_LOG2) + yv.x;
        long long i1 = (xv.y << N_VIRUS_LOG2) + yv.y;
        float r0 = __ldg(recon + i0), r1 = __ldg(recon + i1);
        float v0 = __ldg(dv + i0),    v1 = __ldg(dv + i1);
        float d0 = r0 - v0, d1 = r1 - v1;
        float s = fmaf(d0, d0, d1 * d1);
        acc += (double)s;
    }
    return acc;
}

__global__ __launch_bounds__(256) void gather_se_kernel(
    const float* __restrict__ recon,
    const float* __restrict__ dv,
    const void*  __restrict__ px_raw,
    const void*  __restrict__ py_raw,
    int n_pos,
    const void*  __restrict__ nx_raw,
    const void*  __restrict__ ny_raw,
    int n_neg)
{
    const int tid    = blockIdx.x * blockDim.x + threadIdx.x;
    const int stride = gridDim.x * blockDim.x;
    const int is64   = g_is64;  // uniform across grid

    double pos_acc = 0.0;
    double neg_acc = 0.0;

    if (!is64) {
        // counts are multiples of 4 for this problem; tail loop kept for safety
        int n4p = n_pos >> 2, n4n = n_neg >> 2;
        neg_acc = gather4_i32(recon, dv, (const int4*)nx_raw, (const int4*)ny_raw,
                              n4n, tid, stride, neg_acc);
        pos_acc = gather4_i32(recon, dv, (const int4*)px_raw, (const int4*)py_raw,
                              n4p, tid, stride, pos_acc);
        const int* px = (const int*)px_raw; const int* py = (const int*)py_raw;
        const int* nx = (const int*)nx_raw; const int* ny = (const int*)ny_raw;
        for (int i = (n4n << 2) + tid; i < n_neg; i += stride) {
            unsigned idx = ((unsigned)__ldg(&nx[i]) << N_VIRUS_LOG2) + (unsigned)__ldg(&ny[i]);
            float d = __ldg(recon + idx) - __ldg(dv + idx);
            neg_acc += (double)(d * d);
        }
        for (int i = (n4p << 2) + tid; i < n_pos; i += stride) {
            unsigned idx = ((unsigned)__ldg(&px[i]) << N_VIRUS_LOG2) + (unsigned)__ldg(&py[i]);
            float d = __ldg(recon + idx) - __ldg(dv + idx);
            pos_acc += (double)(d * d);
        }
    } else {
        int n2p = n_pos >> 1, n2n = n_neg >> 1;
        neg_acc = gather2_i64(recon, dv, (const longlong2*)nx_raw, (const longlong2*)ny_raw,
                              n2n, tid, stride, neg_acc);
        pos_acc = gather2_i64(recon, dv, (const longlong2*)px_raw, (const longlong2*)py_raw,
                              n2p, tid, stride, pos_acc);
        const long long* px = (const long long*)px_raw; const long long* py = (const long long*)py_raw;
        const long long* nx = (const long long*)nx_raw; const long long* ny = (const long long*)ny_raw;
        for (int i = (n2n << 1) + tid; i < n_neg; i += stride) {
            long long idx = (__ldg(&nx[i]) << N_VIRUS_LOG2) + __ldg(&ny[i]);
            float d = __ldg(recon + idx) - __ldg(dv + idx);
            neg_acc += (double)(d * d);
        }
        for (int i = (n2p << 1) + tid; i < n_pos; i += stride) {
            long long idx = (__ldg(&px[i]) << N_VIRUS_LOG2) + __ldg(&py[i]);
            float d = __ldg(recon + idx) - __ldg(dv + idx);
            pos_acc += (double)(d * d);
        }
    }

    // warp reduction
    #pragma unroll
    for (int off = 16; off > 0; off >>= 1) {
        pos_acc += __shfl_down_sync(0xFFFFFFFFu, pos_acc, off);
        neg_acc += __shfl_down_sync(0xFFFFFFFFu, neg_acc, off);
    }

    // block reduction: 8 warps -> shared -> warp 0 -> 2 atomics per block
    __shared__ double s_pos[8], s_neg[8];
    int warp = threadIdx.x >> 5, lane = threadIdx.x & 31;
    if (lane == 0) { s_pos[warp] = pos_acc; s_neg[warp] = neg_acc; }
    __syncthreads();
    if (warp == 0) {
        double p = (lane < 8) ? s_pos[lane] : 0.0;
        double n = (lane < 8) ? s_neg[lane] : 0.0;
        #pragma unroll
        for (int off = 4; off > 0; off >>= 1) {
            p += __shfl_down_sync(0xFFFFFFFFu, p, off);
            n += __shfl_down_sync(0xFFFFFFFFu, n, off);
        }
        if (lane == 0) {
            atomicAdd(&g_acc[0], p);
            atomicAdd(&g_acc[1], n);
        }
    }
}

__global__ void finalize_kernel(const float* __restrict__ alpha, float* __restrict__ out) {
    double a = (double)alpha[0];
    out[0] = (float)(g_acc[0] * ((1.0 - a) * 0.5) + g_acc[1] * (a * 0.5));
}

extern "C" void kernel_launch(void* const* d_in, const int* in_sizes, int n_in,
                              void* d_out, int out_size)
{
    const float* recon = (const float*)d_in[0];
    const float* dv    = (const float*)d_in[1];
    const void*  px    = d_in[3];
    const void*  py    = d_in[4];
    const void*  nx    = d_in[5];
    const void*  ny    = d_in[6];
    const float* alpha = (const float*)d_in[7];
    float*       out   = (float*)d_out;

    int n_pos = in_sizes[3];
    int n_neg = in_sizes[5];

    setup_kernel<<<1, 32>>>((const unsigned*)px);

    const int threads = 256;
    const int blocks  = 148 * 8;  // 303K threads; ~1.7 vec4 iters/thread on neg
    gather_se_kernel<<<blocks, threads>>>(recon, dv, px, py, n_pos, nx, ny, n_neg);

    finalize_kernel<<<1, 1>>>(alpha, out);
}

// round 16
// speedup vs baseline: 1.6162x; 1.0485x over previous
#include <cuda_runtime.h>

// DDA_PU_loss: loss = sum_pos (recon-dv)^2 * (1-alpha)/2 + sum_neg (recon-dv)^2 * alpha/2
// Inputs (metadata order):
//  0: drug_virus_reconstruct f32 [8192,16384]
//  1: drug_virus             f32 [8192,16384]
//  2: drug_virus_mask        f32 (unused by reference math)
//  3: pos_x_index  [524288]   int32 OR int64 (detected at runtime)
//  4: pos_y_index  [524288]
//  5: neg_x_index  [2097152]
//  6: neg_y_index  [2097152]
//  7: alpha        f32 scalar
// Output: f32 scalar.

#define N_VIRUS_LOG2 14  // row width 16384, fixed shape

__device__ double g_acc[2];  // [0]=pos_se, [1]=neg_se
__device__ int    g_is64;    // 1 if index arrays are int64, 0 if int32

// Detect index dtype in parallel (1 warp): for little-endian int64 values in
// [0, 8192), every odd 32-bit word (high half) is zero. For int32 uniform in
// [0,8192), P(128 random words all zero) = (1/8192)^128 ~ 0.
__global__ void setup_kernel(const unsigned* __restrict__ px_words) {
    int t = threadIdx.x;  // 0..31
    bool zero = true;
    #pragma unroll
    for (int j = 0; j < 4; j++)
        zero &= (px_words[8 * t + 2 * j + 1] == 0u);
    int all = __all_sync(0xFFFFFFFFu, zero);
    if (t == 0) {
        g_is64  = all ? 1 : 0;
        g_acc[0] = 0.0;
        g_acc[1] = 0.0;
    }
}

// ---- int32 fast path: vec4 index loads, 8 independent gathers per iter ----
__device__ __forceinline__ double gather4_i32(
    const float* __restrict__ recon, const float* __restrict__ dv,
    const int4* __restrict__ x4, const int4* __restrict__ y4,
    int n4, int tid, int stride, double acc)
{
    for (int i = tid; i < n4; i += stride) {
        int4 xv = __ldg(&x4[i]);
        int4 yv = __ldg(&y4[i]);
        unsigned i0 = ((unsigned)xv.x << N_VIRUS_LOG2) + (unsigned)yv.x;
        unsigned i1 = ((unsigned)xv.y << N_VIRUS_LOG2) + (unsigned)yv.y;
        unsigned i2 = ((unsigned)xv.z << N_VIRUS_LOG2) + (unsigned)yv.z;
        unsigned i3 = ((unsigned)xv.w << N_VIRUS_LOG2) + (unsigned)yv.w;
        float r0 = __ldg(recon + i0), r1 = __ldg(recon + i1);
        float r2 = __ldg(recon + i2), r3 = __ldg(recon + i3);
        float v0 = __ldg(dv + i0),    v1 = __ldg(dv + i1);
        float v2 = __ldg(dv + i2),    v3 = __ldg(dv + i3);
        float d0 = r0 - v0, d1 = r1 - v1, d2 = r2 - v2, d3 = r3 - v3;
        float s = fmaf(d0, d0, fmaf(d1, d1, fmaf(d2, d2, d3 * d3)));
        acc += (double)s;
    }
    return acc;
}

// ---- int64 path: vec2 index loads, 4 independent gathers per iter ----
__device__ __forceinline__ double gather2_i64(
    const float* __restrict__ recon, const float* __restrict__ dv,
    const longlong2* __restrict__ x2, const longlong2* __restrict__ y2,
    int n2, int tid, int stride, double acc)
{
    for (int i = tid; i < n2; i += stride) {
        longlong2 xv = __ldg(&x2[i]);
        longlong2 yv = __ldg(&y2[i]);
        long long i0 = (xv.x << N_VIRUS_LOG2) + yv.x;
        long long i1 = (xv.y << N_VIRUS_LOG2) + yv.y;
        float r0 = __ldg(recon + i0), r1 = __ldg(recon + i1);
        float v0 = __ldg(dv + i0),    v1 = __ldg(dv + i1);
        float d0 = r0 - v0, d1 = r1 - v1;
        float s = fmaf(d0, d0, d1 * d1);
        acc += (double)s;
    }
    return acc;
}

__global__ __launch_bounds__(256) void gather_se_kernel(
    const float* __restrict__ recon,
    const float* __restrict__ dv,
    const void*  __restrict__ px_raw,
    const void*  __restrict__ py_raw,
    int n_pos,
    const void*  __restrict__ nx_raw,
    const void*  __restrict__ ny_raw,
    int n_neg)
{
    const int tid    = blockIdx.x * blockDim.x + threadIdx.x;
    const int stride = gridDim.x * blockDim.x;
    const int is64   = g_is64;  // uniform across grid

    double pos_acc = 0.0;
    double neg_acc = 0.0;

    if (!is64) {
        // counts are multiples of 4 for this problem; tail loop kept for safety
        int n4p = n_pos >> 2, n4n = n_neg >> 2;
        neg_acc = gather4_i32(recon, dv, (const int4*)nx_raw, (const int4*)ny_raw,
                              n4n, tid, stride, neg_acc);
        pos_acc = gather4_i32(recon, dv, (const int4*)px_raw, (const int4*)py_raw,
                              n4p, tid, stride, pos_acc);
        const int* px = (const int*)px_raw; const int* py = (const int*)py_raw;
        const int* nx = (const int*)nx_raw; const int* ny = (const int*)ny_raw;
        for (int i = (n4n << 2) + tid; i < n_neg; i += stride) {
            unsigned idx = ((unsigned)__ldg(&nx[i]) << N_VIRUS_LOG2) + (unsigned)__ldg(&ny[i]);
            float d = __ldg(recon + idx) - __ldg(dv + idx);
            neg_acc += (double)(d * d);
        }
        for (int i = (n4p << 2) + tid; i < n_pos; i += stride) {
            unsigned idx = ((unsigned)__ldg(&px[i]) << N_VIRUS_LOG2) + (unsigned)__ldg(&py[i]);
            float d = __ldg(recon + idx) - __ldg(dv + idx);
            pos_acc += (double)(d * d);
        }
    } else {
        int n2p = n_pos >> 1, n2n = n_neg >> 1;
        neg_acc = gather2_i64(recon, dv, (const longlong2*)nx_raw, (const longlong2*)ny_raw,
                              n2n, tid, stride, neg_acc);
        pos_acc = gather2_i64(recon, dv, (const longlong2*)px_raw, (const longlong2*)py_raw,
                              n2p, tid, stride, pos_acc);
        const long long* px = (const long long*)px_raw; const long long* py = (const long long*)py_raw;
        const long long* nx = (const long long*)nx_raw; const long long* ny = (const long long*)ny_raw;
        for (int i = (n2n << 1) + tid; i < n_neg; i += stride) {
            long long idx = (__ldg(&nx[i]) << N_VIRUS_LOG2) + __ldg(&ny[i]);
            float d = __ldg(recon + idx) - __ldg(dv + idx);
            neg_acc += (double)(d * d);
        }
        for (int i = (n2p << 1) + tid; i < n_pos; i += stride) {
            long long idx = (__ldg(&px[i]) << N_VIRUS_LOG2) + __ldg(&py[i]);
            float d = __ldg(recon + idx) - __ldg(dv + idx);
            pos_acc += (double)(d * d);
        }
    }

    // warp reduction
    #pragma unroll
    for (int off = 16; off > 0; off >>= 1) {
        pos_acc += __shfl_down_sync(0xFFFFFFFFu, pos_acc, off);
        neg_acc += __shfl_down_sync(0xFFFFFFFFu, neg_acc, off);
    }

    // block reduction: 8 warps -> shared -> warp 0 -> 2 atomics per block
    __shared__ double s_pos[8], s_neg[8];
    int warp = threadIdx.x >> 5, lane = threadIdx.x & 31;
    if (lane == 0) { s_pos[warp] = pos_acc; s_neg[warp] = neg_acc; }
    __syncthreads();
    if (warp == 0) {
        double p = (lane < 8) ? s_pos[lane] : 0.0;
        double n = (lane < 8) ? s_neg[lane] : 0.0;
        #pragma unroll
        for (int off = 4; off > 0; off >>= 1) {
            p += __shfl_down_sync(0xFFFFFFFFu, p, off);
            n += __shfl_down_sync(0xFFFFFFFFu, n, off);
        }
        if (lane == 0) {
            atomicAdd(&g_acc[0], p);
            atomicAdd(&g_acc[1], n);
        }
    }
}

__global__ void finalize_kernel(const float* __restrict__ alpha, float* __restrict__ out) {
    double a = (double)alpha[0];
    out[0] = (float)(g_acc[0] * ((1.0 - a) * 0.5) + g_acc[1] * (a * 0.5));
}

extern "C" void kernel_launch(void* const* d_in, const int* in_sizes, int n_in,
                              void* d_out, int out_size)
{
    const float* recon = (const float*)d_in[0];
    const float* dv    = (const float*)d_in[1];
    const void*  px    = d_in[3];
    const void*  py    = d_in[4];
    const void*  nx    = d_in[5];
    const void*  ny    = d_in[6];
    const float* alpha = (const float*)d_in[7];
    float*       out   = (float*)d_out;

    int n_pos = in_sizes[3];
    int n_neg = in_sizes[5];

    setup_kernel<<<1, 32>>>((const unsigned*)px);

    const int threads = 256;
    const int blocks  = 148 * 8;  // 303K threads; ~1.7 vec4 iters/thread on neg
    gather_se_kernel<<<blocks, threads>>>(recon, dv, px, py, n_pos, nx, ny, n_neg);

    finalize_kernel<<<1, 1>>>(alpha, out);
}